// round 10
// baseline (speedup 1.0000x reference)
#include <cuda_runtime.h>

typedef unsigned long long ull;

#define IMG_W 512
#define IMG_H 512
#define NPLANES 48            // 16 batch * 3 channels
#define NSTRIPS 12            // strips per plane
#define STRIP_ROWS 44         // 11 chunks of 4 rows (rows >= 512 masked)
#define NBLOCKS (NPLANES * NSTRIPS)   // 576 blocks, occ=4 -> one wave
#define NTHREADS 128          // each thread owns 4 adjacent columns
#define ROWQ 128              // ulonglong2 (4 floats) per 512-px image row
#define NCHUNKS 11
#define CROWS 4               // output rows per chunk
#define NFIELDS 4             // x, y, u=x^2+y^2, v=x*y

#define SSIM_C1 0.0001f
#define SSIM_C2 0.0009f

// 1D gaussian (sigma=1.5, 11 taps, normalized) as literals -> FFMA-imm (rt=1)
#define G0 0.00102836f
#define G1 0.00759863f
#define G2 0.03600078f
#define G3 0.10936075f
#define G4 0.21300559f
#define G5 0.26601179f

#define FULLM 0xffffffffu

__device__ double g_partials[NBLOCKS];
__device__ unsigned g_arrive = 0;

__device__ __forceinline__ ull pack2(float x, float y) {
    ull r; asm("mov.b64 %0, {%1,%2};" : "=l"(r) : "f"(x), "f"(y)); return r;
}
__device__ __forceinline__ ull mul2(ull a, ull b) {
    ull d; asm("mul.rn.f32x2 %0, %1, %2;" : "=l"(d) : "l"(a), "l"(b)); return d;
}
__device__ __forceinline__ ull fma2(ull a, ull b, ull c) {
    ull d; asm("fma.rn.f32x2 %0, %1, %2, %3;" : "=l"(d) : "l"(a), "l"(b), "l"(c)); return d;
}
__device__ __forceinline__ float lo2(ull v) { float x, y;
    asm("mov.b64 {%0,%1}, %2;" : "=f"(x), "=f"(y) : "l"(v)); return x; }
__device__ __forceinline__ float hi2(ull v) { float x, y;
    asm("mov.b64 {%0,%1}, %2;" : "=f"(x), "=f"(y) : "l"(v)); return y; }
__device__ __forceinline__ void un2(ull v, float& x, float& y) {
    asm("mov.b64 {%0,%1}, %2;" : "=f"(x), "=f"(y) : "l"(v)); }

// 11-tap conv with immediate weights (FFMA-imm, rt=1)
__device__ __forceinline__ float conv11(float e0, float e1, float e2, float e3,
                                        float e4, float e5, float e6, float e7,
                                        float e8, float e9, float e10) {
    float a = G0 * e0;
    a = fmaf(G1, e1, a);  a = fmaf(G2, e2, a);  a = fmaf(G3, e3, a);
    a = fmaf(G4, e4, a);  a = fmaf(G5, e5, a);  a = fmaf(G4, e6, a);
    a = fmaf(G3, e7, a);  a = fmaf(G2, e8, a);  a = fmaf(G1, e9, a);
    a = fmaf(G0, e10, a);
    return a;
}

// SSIM from the 4 convolved fields: mu1, mu2, euu=E[x^2+y^2], exy=E[xy]
__device__ __forceinline__ float ssim_px(float mu1, float mu2, float euu, float exy) {
    float msq = mu1 * mu1;
    msq = fmaf(mu2, mu2, msq);           // mu1^2 + mu2^2
    float m12 = mu1 * mu2;
    float ssum = euu - msq;              // sig1^2 + sig2^2
    float s12  = exy - m12;
    float num = fmaf(2.0f, m12, SSIM_C1) * fmaf(2.0f, s12, SSIM_C2);
    float den = (msq + SSIM_C1) * (ssum + SSIM_C2);
    return __fdividef(num, den);
}

#define EIDX(f, j, s) ((((f) * CROWS + (j)) << 1) | (s))

__global__ void __launch_bounds__(NTHREADS, 4)
ssim_main(const float* __restrict__ img1, const float* __restrict__ img2,
          float* __restrict__ out) {
    // Edge exchange buffer: [parity][warp slot 0..5][lane class][field*row*2]
    // warp slot ws = warp+1; slots 0 and 5 are permanent zeros (image col halo).
    // lane class: 0 = lane0, 1 = lane1, 2 = lane30, 3 = lane31.
    __shared__ ull ebuf[2][6][4][NFIELDS * CROWS * 2];
    __shared__ float wsums[NTHREADS / 32];
    __shared__ int is_last;

    const int bx = blockIdx.x;
    const int plane = bx / NSTRIPS;
    const int strip = bx - plane * NSTRIPS;
    const int r0 = strip * STRIP_ROWS;
    const int t = threadIdx.x;
    const int lane = t & 31;
    const int warp = t >> 5;

    // Zero the virtual-warp slots (0 and 5) of both parities once.
    // 2 parities x 2 slots x 4 classes x 32 ulls = 512 ulls.
    for (int idx = t; idx < 512; idx += NTHREADS) {
        int p = idx >> 8, rem = idx & 255;
        int sl = (rem >> 7) ? 5 : 0, rem2 = rem & 127;
        ebuf[p][sl][rem2 >> 5][rem2 & 31] = 0ull;
    }

    // Thread t owns cols 4t..4t+3 -> one ulonglong2 (two f32x2 lanes) per image row
    const ulonglong2* __restrict__ p1 =
        (const ulonglong2*)img1 + (size_t)plane * (IMG_H * ROWQ) + t;
    const ulonglong2* __restrict__ p2 =
        (const ulonglong2*)img2 + (size_t)plane * (IMG_H * ROWQ) + t;

    const ull Wp[6] = {pack2(G0, G0), pack2(G1, G1), pack2(G2, G2),
                       pack2(G3, G3), pack2(G4, G4), pack2(G5, G5)};

    auto loadrow = [&](int row, ulonglong2& A, ulonglong2& B) {
        if ((unsigned)row < IMG_H) {
            A = p1[(size_t)row * ROWQ];
            B = p2[(size_t)row * ROWQ];
        } else { A.x = A.y = B.x = B.y = 0ull; }
    };

    // Lane class for edge exchange (-1 = interior)
    const int cls = (lane == 0) ? 0 : (lane == 1) ? 1 :
                    (lane == 30) ? 2 : (lane == 31) ? 3 : -1;

    float accv = 0.0f;

    ulonglong2 A, B;
    loadrow(r0 - 5, A, B);   // prefetch first input row

    for (int c = 0; c < NCHUNKS; ++c) {
        const int R = r0 + c * CROWS;    // first output row of this chunk
        const int par = c & 1;

        // ---- Vertical scatter: 14 input rows -> 4 output accumulators,
        //      two f32x2 column streams per thread ----
        ull acc[NFIELDS][CROWS][2];
#pragma unroll
        for (int f = 0; f < NFIELDS; ++f)
#pragma unroll
            for (int j = 0; j < CROWS; ++j) { acc[f][j][0] = 0ull; acc[f][j][1] = 0ull; }

#pragma unroll
        for (int i = 0; i < CROWS + 10; ++i) {
            const ulonglong2 PA = A, PB = B;     // input row R-5+i
            {   // prefetch next row (i==13 prefetches next chunk's first row R-1)
                const int nrow = (i < CROWS + 9) ? (R - 4 + i) : (R - 1);
                loadrow(nrow, A, B);
            }
            const ull pu0 = fma2(PA.x, PA.x, mul2(PB.x, PB.x));
            const ull pv0 = mul2(PA.x, PB.x);
            const ull pu1 = fma2(PA.y, PA.y, mul2(PB.y, PB.y));
            const ull pv1 = mul2(PA.y, PB.y);

            const int jlo = (i - 10 > 0) ? (i - 10) : 0;
            const int jhi = (i < CROWS - 1) ? i : (CROWS - 1);
#pragma unroll
            for (int j = jlo; j <= jhi; ++j) {
                const int k = i - j;                    // 0..10
                const int wi = (k < 6) ? k : 10 - k;    // symmetric weight
                acc[0][j][0] = fma2(PA.x, Wp[wi], acc[0][j][0]);
                acc[0][j][1] = fma2(PA.y, Wp[wi], acc[0][j][1]);
                acc[1][j][0] = fma2(PB.x, Wp[wi], acc[1][j][0]);
                acc[1][j][1] = fma2(PB.y, Wp[wi], acc[1][j][1]);
                acc[2][j][0] = fma2(pu0, Wp[wi], acc[2][j][0]);
                acc[2][j][1] = fma2(pu1, Wp[wi], acc[2][j][1]);
                acc[3][j][0] = fma2(pv0, Wp[wi], acc[3][j][0]);
                acc[3][j][1] = fma2(pv1, Wp[wi], acc[3][j][1]);
            }
        }

        // ---- Edge lanes publish their V columns for cross-warp halo ----
        if (cls >= 0) {
            ull* dst = ebuf[par][warp + 1][cls];
#pragma unroll
            for (int f = 0; f < NFIELDS; ++f)
#pragma unroll
                for (int j = 0; j < CROWS; ++j) {
                    dst[EIDX(f, j, 0)] = acc[f][j][0];
                    dst[EIDX(f, j, 1)] = acc[f][j][1];
                }
        }
        __syncthreads();   // single barrier per chunk (parity-double-buffered)

        // ---- Horizontal + SSIM on own 4 columns, via warp shuffles ----
#pragma unroll
        for (int j = 0; j < CROWS; ++j) {
            float h[NFIELDS][4];
#pragma unroll
            for (int f = 0; f < NFIELDS; ++f) {
                float e5, e6, e7, e8;
                un2(acc[f][j][0], e5, e6);     // cols 4t, 4t+1
                un2(acc[f][j][1], e7, e8);     // cols 4t+2, 4t+3
                // Window idx = col - (4t-5): own cols are e5..e8
                float e1 = __shfl_up_sync(FULLM, e5, 1);
                float e2 = __shfl_up_sync(FULLM, e6, 1);
                float e3 = __shfl_up_sync(FULLM, e7, 1);
                float e4 = __shfl_up_sync(FULLM, e8, 1);
                float e0 = __shfl_up_sync(FULLM, e8, 2);
                float e9  = __shfl_down_sync(FULLM, e5, 1);
                float e10 = __shfl_down_sync(FULLM, e6, 1);
                float e11 = __shfl_down_sync(FULLM, e7, 1);
                float e12 = __shfl_down_sync(FULLM, e8, 1);
                float e13 = __shfl_down_sync(FULLM, e5, 2);
                // Cross-warp fixups from the edge buffer
                if (lane == 0) {
                    const ull* m1p = ebuf[par][warp][3];   // thread t-1 (prev warp lane31)
                    const ull* m2p = ebuf[par][warp][2];   // thread t-2 (prev warp lane30)
                    un2(m1p[EIDX(f, j, 0)], e1, e2);
                    un2(m1p[EIDX(f, j, 1)], e3, e4);
                    e0 = hi2(m2p[EIDX(f, j, 1)]);
                } else if (lane == 1) {
                    e0 = hi2(ebuf[par][warp][3][EIDX(f, j, 1)]);   // t-2 = prev warp lane31
                }
                if (lane == 31) {
                    const ull* q1p = ebuf[par][warp + 2][0];   // t+1 (next warp lane0)
                    const ull* q2p = ebuf[par][warp + 2][1];   // t+2 (next warp lane1)
                    un2(q1p[EIDX(f, j, 0)], e9, e10);
                    un2(q1p[EIDX(f, j, 1)], e11, e12);
                    e13 = lo2(q2p[EIDX(f, j, 0)]);
                } else if (lane == 30) {
                    e13 = lo2(ebuf[par][warp + 2][0][EIDX(f, j, 0)]);   // t+2 col0
                }
                h[f][0] = conv11(e0, e1, e2, e3, e4, e5, e6, e7, e8, e9, e10);
                h[f][1] = conv11(e1, e2, e3, e4, e5, e6, e7, e8, e9, e10, e11);
                h[f][2] = conv11(e2, e3, e4, e5, e6, e7, e8, e9, e10, e11, e12);
                h[f][3] = conv11(e3, e4, e5, e6, e7, e8, e9, e10, e11, e12, e13);
            }
            if (R + j < IMG_H) {
#pragma unroll
                for (int p = 0; p < 4; ++p)
                    accv += ssim_px(h[0][p], h[1][p], h[2][p], h[3][p]);
            }
        }
    }

    // ---- Deterministic block reduction ----
#pragma unroll
    for (int off = 16; off; off >>= 1)
        accv += __shfl_xor_sync(FULLM, accv, off);
    if ((t & 31) == 0) wsums[t >> 5] = accv;
    __syncthreads();
    if (t == 0) {
        float s = 0.0f;
#pragma unroll
        for (int i = 0; i < NTHREADS / 32; ++i) s += wsums[i];
        g_partials[bx] = (double)s;
        __threadfence();
        unsigned old = atomicAdd(&g_arrive, 1u);
        is_last = (old == NBLOCKS - 1) ? 1 : 0;
    }
    __syncthreads();

    // ---- Fused deterministic finalize (last-arriving block, warp 0) ----
    if (is_last && t < 32) {
        __threadfence();
        double s = 0.0;
#pragma unroll
        for (int k = 0; k < NBLOCKS / 32; ++k) s += g_partials[t + 32 * k];
#pragma unroll
        for (int off = 16; off; off >>= 1)
            s += __shfl_xor_sync(FULLM, s, off);
        if (t == 0) {
            out[0] = (float)(1.0 - s / 12582912.0);   // 16*3*512*512
            g_arrive = 0;   // reset for next graph replay
        }
    }
}

extern "C" void kernel_launch(void* const* d_in, const int* in_sizes, int n_in,
                              void* d_out, int out_size) {
    const float* img1 = (const float*)d_in[0];
    const float* img2 = (const float*)d_in[1];
    // d_in[2] (gaussian window) is deterministic; weights baked in as immediates.
    ssim_main<<<NBLOCKS, NTHREADS>>>(img1, img2, (float*)d_out);
}

// round 11
// speedup vs baseline: 1.4684x; 1.4684x over previous
#include <cuda_runtime.h>

typedef unsigned long long ull;

#define IMG_W 512
#define IMG_H 512
#define NPLANES 48            // 16 batch * 3 channels
#define NSTRIPS 12            // strips per plane
#define STRIP_ROWS 44         // 11 chunks of 4 rows (rows >= 512 masked)
#define NBLOCKS (NPLANES * NSTRIPS)   // 576 blocks, occ=4 -> one wave
#define NTHREADS 128          // each thread owns 4 adjacent columns
#define ROWQ 128              // ulonglong2 (4 floats) per 512-px image row
#define NCHUNKS 11
#define CROWS 4               // output rows per chunk (2 row-pairs)
#define NFIELDS 4             // x, y, u=x^2+y^2, v=x*y

// Interleaved V layout: entry e (= col e-8) is a float2 (row0,row1) of a row
// pair. Entries grouped by 4 (one thread's cols); each 32B group padded to
// 48B so horizontal lane stride is 48B -> conflict-free LDS.128.
// phys_ull(e) = 6*(e>>2) + (e&3). 528 entries -> 132 groups -> 792 ull/array.
#define ARRU 792
#define NARR (NFIELDS * 2)    // 4 fields x 2 row-pairs
#define SMEM_BYTES (NARR * ARRU * 8)   // 50688 -> 4 blocks/SM fit

#define SSIM_C1 0.0001f
#define SSIM_C2 0.0009f

// 1D gaussian (sigma=1.5, 11 taps, normalized) as literals
#define G0 0.00102836f
#define G1 0.00759863f
#define G2 0.03600078f
#define G3 0.10936075f
#define G4 0.21300559f
#define G5 0.26601179f

#define FULLM 0xffffffffu

__device__ double g_partials[NBLOCKS];
__device__ unsigned g_arrive = 0;

__device__ __forceinline__ ull pack2(float x, float y) {
    ull r; asm("mov.b64 %0, {%1,%2};" : "=l"(r) : "f"(x), "f"(y)); return r;
}
__device__ __forceinline__ void un2(ull v, float& x, float& y) {
    asm("mov.b64 {%0,%1}, %2;" : "=f"(x), "=f"(y) : "l"(v));
}
__device__ __forceinline__ ull mul2(ull a, ull b) {
    ull d; asm("mul.rn.f32x2 %0, %1, %2;" : "=l"(d) : "l"(a), "l"(b)); return d;
}
__device__ __forceinline__ ull add2(ull a, ull b) {
    ull d; asm("add.rn.f32x2 %0, %1, %2;" : "=l"(d) : "l"(a), "l"(b)); return d;
}
__device__ __forceinline__ ull fma2(ull a, ull b, ull c) {
    ull d; asm("fma.rn.f32x2 %0, %1, %2, %3;" : "=l"(d) : "l"(a), "l"(b), "l"(c)); return d;
}
__device__ __forceinline__ float rcpa(float x) {
    float r; asm("rcp.approx.f32 %0, %1;" : "=f"(r) : "f"(x)); return r;
}

__global__ void __launch_bounds__(NTHREADS, 4)
ssim_main(const float* __restrict__ img1, const float* __restrict__ img2,
          float* __restrict__ out) {
    extern __shared__ ull Vs[];
    __shared__ float wsums[NTHREADS / 32];
    __shared__ int is_last;

    const int bx = blockIdx.x;
    const int plane = bx / NSTRIPS;
    const int strip = bx - plane * NSTRIPS;
    const int r0 = strip * STRIP_ROWS;
    const int t = threadIdx.x;

    // Zero halo groups 0,1 (cols -8..-1) and 130,131 (cols 512..519) of all
    // 8 arrays (pads included): 8 * 4 * 6 = 192 ulls, written once.
    for (int idx = t; idx < NARR * 24; idx += NTHREADS) {
        const int ar = idx / 24, rem = idx % 24;
        const int gi = rem / 6, u = rem % 6;
        const int grp = (gi < 2) ? gi : (128 + gi);
        Vs[ar * ARRU + grp * 6 + u] = 0ull;
    }

    // Thread t owns cols 4t..4t+3 -> one ulonglong2 (two f32x2 lanes) per row
    const ulonglong2* __restrict__ p1 =
        (const ulonglong2*)img1 + (size_t)plane * (IMG_H * ROWQ) + t;
    const ulonglong2* __restrict__ p2 =
        (const ulonglong2*)img2 + (size_t)plane * (IMG_H * ROWQ) + t;

    const ull Wp[6] = {pack2(G0, G0), pack2(G1, G1), pack2(G2, G2),
                       pack2(G3, G3), pack2(G4, G4), pack2(G5, G5)};
    const ull C1_2 = pack2(SSIM_C1, SSIM_C1);
    const ull C2_2 = pack2(SSIM_C2, SSIM_C2);
    const ull TWO2 = pack2(2.0f, 2.0f);
    const ull NEG1 = pack2(-1.0f, -1.0f);

    auto loadrow = [&](int row, ulonglong2& A, ulonglong2& B) {
        if ((unsigned)row < IMG_H) {
            A = p1[(size_t)row * ROWQ];
            B = p2[(size_t)row * ROWQ];
        } else { A.x = A.y = B.x = B.y = 0ull; }
    };

    // Packed SSIM for a (row0,row1) pair of one pixel column
    auto ssim2 = [&](ull mu1, ull mu2, ull euu, ull exy) -> ull {
        ull msq = mul2(mu1, mu1);
        msq = fma2(mu2, mu2, msq);            // mu1^2 + mu2^2
        ull m12 = mul2(mu1, mu2);
        ull ssum = fma2(msq, NEG1, euu);      // euu - msq
        ull s12  = fma2(m12, NEG1, exy);      // exy - m12
        ull num = mul2(fma2(TWO2, m12, C1_2), fma2(TWO2, s12, C2_2));
        ull den = mul2(add2(msq, C1_2), add2(ssum, C2_2));
        float dl, dh; un2(den, dl, dh);
        ull r = pack2(rcpa(dl), rcpa(dh));    // same math as __fdividef
        return mul2(num, r);
    };

    ull acc2 = 0ull;   // packed SSIM accumulator

    ulonglong2 A, B;
    loadrow(r0 - 5, A, B);   // prefetch first input row

    __syncthreads();         // halo zeros visible

    for (int c = 0; c < NCHUNKS; ++c) {
        const int R = r0 + c * CROWS;    // first output row of this chunk

        // ---- Vertical scatter: 14 input rows -> 4 output rows,
        //      two f32x2 column streams per thread (f32x2 over col pairs) ----
        ull acc[NFIELDS][CROWS][2];
#pragma unroll
        for (int f = 0; f < NFIELDS; ++f)
#pragma unroll
            for (int j = 0; j < CROWS; ++j) { acc[f][j][0] = 0ull; acc[f][j][1] = 0ull; }

#pragma unroll
        for (int i = 0; i < CROWS + 10; ++i) {
            const ulonglong2 PA = A, PB = B;     // input row R-5+i
            {   // prefetch next row (i==13 prefetches next chunk's first row R-1)
                const int nrow = (i < CROWS + 9) ? (R - 4 + i) : (R - 1);
                loadrow(nrow, A, B);
            }
            const ull pu0 = fma2(PA.x, PA.x, mul2(PB.x, PB.x));
            const ull pv0 = mul2(PA.x, PB.x);
            const ull pu1 = fma2(PA.y, PA.y, mul2(PB.y, PB.y));
            const ull pv1 = mul2(PA.y, PB.y);

            const int jlo = (i - 10 > 0) ? (i - 10) : 0;
            const int jhi = (i < CROWS - 1) ? i : (CROWS - 1);
#pragma unroll
            for (int j = jlo; j <= jhi; ++j) {
                const int k = i - j;                    // 0..10
                const int wi = (k < 6) ? k : 10 - k;    // symmetric weight
                acc[0][j][0] = fma2(PA.x, Wp[wi], acc[0][j][0]);
                acc[0][j][1] = fma2(PA.y, Wp[wi], acc[0][j][1]);
                acc[1][j][0] = fma2(PB.x, Wp[wi], acc[1][j][0]);
                acc[1][j][1] = fma2(PB.y, Wp[wi], acc[1][j][1]);
                acc[2][j][0] = fma2(pu0, Wp[wi], acc[2][j][0]);
                acc[2][j][1] = fma2(pu1, Wp[wi], acc[2][j][1]);
                acc[3][j][0] = fma2(pv0, Wp[wi], acc[3][j][0]);
                acc[3][j][1] = fma2(pv1, Wp[wi], acc[3][j][1]);
            }
        }

        // ---- Store with 2x2 register transpose: column entries (row0,row1),
        //      thread t's 4 cols = exactly group t+2 -> two STS.128, 48B lane
        //      stride, conflict-free ----
#pragma unroll
        for (int rp = 0; rp < 2; ++rp) {
#pragma unroll
            for (int f = 0; f < NFIELDS; ++f) {
                float a0, a1, b0, b1, c0, c1, d0, d1;
                un2(acc[f][2 * rp][0], a0, a1);       // row0: cols 4t,4t+1
                un2(acc[f][2 * rp + 1][0], b0, b1);   // row1: cols 4t,4t+1
                un2(acc[f][2 * rp][1], c0, c1);       // row0: cols 4t+2,4t+3
                un2(acc[f][2 * rp + 1][1], d0, d1);
                ulonglong2 v0, v1;
                v0.x = pack2(a0, b0);   // col 4t   (r0,r1)
                v0.y = pack2(a1, b1);   // col 4t+1
                v1.x = pack2(c0, d0);   // col 4t+2
                v1.y = pack2(c1, d1);   // col 4t+3
                ull* arr = Vs + (f * 2 + rp) * ARRU + (t + 2) * 6;
                *(ulonglong2*)(arr) = v0;
                *(ulonglong2*)(arr + 2) = v1;
            }
        }
        __syncthreads();   // V entries visible

        // ---- Horizontal + SSIM, packed over the row pair ----
        // rd 0 -> row-pair 0, rd 1 -> row-pair 1; g = t (4 cols per job)
#pragma unroll
        for (int rd = 0; rd < 2; ++rd) {
            const int rp = rd;
            const int g = t;
            ull h[NFIELDS][4];
#pragma unroll
            for (int f = 0; f < NFIELDS; ++f) {
                const ull* bp = Vs + (f * 2 + rp) * ARRU + 6 * g;
                // E[m] = entry 4g+2+m (cols 4g-6..4g+9); 8 conflict-free LDS.128
                ull E[16];
                ulonglong2 q;
                q = *(const ulonglong2*)(bp + 2);  E[0] = q.x;  E[1] = q.y;
                q = *(const ulonglong2*)(bp + 6);  E[2] = q.x;  E[3] = q.y;
                q = *(const ulonglong2*)(bp + 8);  E[4] = q.x;  E[5] = q.y;
                q = *(const ulonglong2*)(bp + 12); E[6] = q.x;  E[7] = q.y;
                q = *(const ulonglong2*)(bp + 14); E[8] = q.x;  E[9] = q.y;
                q = *(const ulonglong2*)(bp + 18); E[10] = q.x; E[11] = q.y;
                q = *(const ulonglong2*)(bp + 20); E[12] = q.x; E[13] = q.y;
                q = *(const ulonglong2*)(bp + 24); E[14] = q.x; E[15] = q.y;
#pragma unroll
                for (int p = 0; p < 4; ++p) {
                    // out col 4g+p: window cols 4g+p-5..4g+p+5 = E[p+1..p+11]
                    ull s = mul2(E[p + 1], Wp[0]);
#pragma unroll
                    for (int k = 1; k <= 10; ++k) {
                        const int wi = (k < 6) ? k : 10 - k;
                        s = fma2(E[p + 1 + k], Wp[wi], s);
                    }
                    h[f][p] = s;
                }
            }
            if (R + 2 * rp < IMG_H) {   // pairs never straddle the image edge
#pragma unroll
                for (int p = 0; p < 4; ++p)
                    acc2 = add2(acc2, ssim2(h[0][p], h[1][p], h[2][p], h[3][p]));
            }
        }
        __syncthreads();   // horizontal reads done before next chunk's STS
    }

    // ---- Deterministic block reduction ----
    float aclo, achi; un2(acc2, aclo, achi);
    float accv = aclo + achi;
#pragma unroll
    for (int off = 16; off; off >>= 1)
        accv += __shfl_xor_sync(FULLM, accv, off);
    if ((t & 31) == 0) wsums[t >> 5] = accv;
    __syncthreads();
    if (t == 0) {
        float s = 0.0f;
#pragma unroll
        for (int i = 0; i < NTHREADS / 32; ++i) s += wsums[i];
        g_partials[bx] = (double)s;
        __threadfence();
        unsigned old = atomicAdd(&g_arrive, 1u);
        is_last = (old == NBLOCKS - 1) ? 1 : 0;
    }
    __syncthreads();

    // ---- Fused deterministic finalize (last-arriving block, warp 0) ----
    if (is_last && t < 32) {
        __threadfence();
        double s = 0.0;
#pragma unroll
        for (int k = 0; k < NBLOCKS / 32; ++k) s += g_partials[t + 32 * k];
#pragma unroll
        for (int off = 16; off; off >>= 1)
            s += __shfl_xor_sync(FULLM, s, off);
        if (t == 0) {
            out[0] = (float)(1.0 - s / 12582912.0);   // 16*3*512*512
            g_arrive = 0;   // reset for next graph replay
        }
    }
}

extern "C" void kernel_launch(void* const* d_in, const int* in_sizes, int n_in,
                              void* d_out, int out_size) {
    const float* img1 = (const float*)d_in[0];
    const float* img2 = (const float*)d_in[1];
    // d_in[2] (gaussian window) is deterministic; weights baked in as immediates.
    cudaFuncSetAttribute(ssim_main, cudaFuncAttributeMaxDynamicSharedMemorySize,
                         SMEM_BYTES);
    ssim_main<<<NBLOCKS, NTHREADS, SMEM_BYTES>>>(img1, img2, (float*)d_out);
}

// round 12
// speedup vs baseline: 1.4735x; 1.0035x over previous
#include <cuda_runtime.h>

typedef unsigned long long ull;

#define IMG_W 512
#define IMG_H 512
#define NPLANES 48            // 16 batch * 3 channels
#define NSTRIPS 12            // strips per plane
#define STRIP_ROWS 44         // 11 chunks of 4 rows (rows >= 512 masked)
#define NBLOCKS (NPLANES * NSTRIPS)   // 576 blocks, occ=4 -> one wave
#define NTHREADS 128          // each thread owns 4 adjacent columns
#define ROWQ 128              // ulonglong2 (4 floats) per 512-px image row
#define NCHUNKS 11
#define CROWS 4               // output rows per chunk
#define NFIELDS 4             // x, y, u=x^2+y^2, v=x*y

// V row layout: position of col c = c + 6 (6-float left halo). Positions
// 0..5 = cols -6..-1 (zero), 518..527 = cols 512..521 (zero). A horizontal
// job's 4 outputs (cols 4g..4g+3) need window positions 4g+1..4g+14, which
// fit in FOUR aligned LDS.128 at positions 4g..4g+15 (halo-8 needed five).
#define ROWF 528
#define SMEM_FLOATS (NFIELDS * CROWS * ROWF)
#define SMEM_BYTES (SMEM_FLOATS * 4)   // 33792 -> 4 blocks/SM fit

#define SSIM_C1 0.0001f
#define SSIM_C2 0.0009f

// 1D gaussian (sigma=1.5, 11 taps, normalized) as literals -> FFMA-imm (rt=1)
#define G0 0.00102836f
#define G1 0.00759863f
#define G2 0.03600078f
#define G3 0.10936075f
#define G4 0.21300559f
#define G5 0.26601179f

#define FULLM 0xffffffffu

__device__ double g_partials[NBLOCKS];
__device__ unsigned g_arrive = 0;

__device__ __forceinline__ ull pack2(float x, float y) {
    ull r; asm("mov.b64 %0, {%1,%2};" : "=l"(r) : "f"(x), "f"(y)); return r;
}
__device__ __forceinline__ ull mul2(ull a, ull b) {
    ull d; asm("mul.rn.f32x2 %0, %1, %2;" : "=l"(d) : "l"(a), "l"(b)); return d;
}
__device__ __forceinline__ ull fma2(ull a, ull b, ull c) {
    ull d; asm("fma.rn.f32x2 %0, %1, %2, %3;" : "=l"(d) : "l"(a), "l"(b), "l"(c)); return d;
}

// Horizontal 11-tap conv for 4 px (cols 4g..4g+3).
// rp = row base + 4g floats (16B aligned); FOUR LDS.128, lane stride 16B ->
// conflict-free. Output col 4g+p uses window e[p+1..p+11].
__device__ __forceinline__ void hconv4(const float* __restrict__ rp, float o[4]) {
    float e[16];
    const float4* q = (const float4*)rp;
#pragma unroll
    for (int i = 0; i < 4; ++i) {
        float4 v = q[i];
        e[4 * i] = v.x; e[4 * i + 1] = v.y; e[4 * i + 2] = v.z; e[4 * i + 3] = v.w;
    }
#pragma unroll
    for (int p = 0; p < 4; ++p) {
        float a = G0 * e[p + 1];
        a = fmaf(G1, e[p + 2], a);  a = fmaf(G2, e[p + 3], a);
        a = fmaf(G3, e[p + 4], a);  a = fmaf(G4, e[p + 5], a);
        a = fmaf(G5, e[p + 6], a);  a = fmaf(G4, e[p + 7], a);
        a = fmaf(G3, e[p + 8], a);  a = fmaf(G2, e[p + 9], a);
        a = fmaf(G1, e[p + 10], a); a = fmaf(G0, e[p + 11], a);
        o[p] = a;
    }
}

// SSIM from the 4 convolved fields: mu1, mu2, euu=E[x^2+y^2], exy=E[xy]
__device__ __forceinline__ float ssim_px(float mu1, float mu2, float euu, float exy) {
    float msq = mu1 * mu1;
    msq = fmaf(mu2, mu2, msq);           // mu1^2 + mu2^2
    float m12 = mu1 * mu2;
    float ssum = euu - msq;              // sig1^2 + sig2^2
    float s12  = exy - m12;
    float num = fmaf(2.0f, m12, SSIM_C1) * fmaf(2.0f, s12, SSIM_C2);
    float den = (msq + SSIM_C1) * (ssum + SSIM_C2);
    return __fdividef(num, den);
}

__global__ void __launch_bounds__(NTHREADS, 4)
ssim_main(const float* __restrict__ img1, const float* __restrict__ img2,
          float* __restrict__ out) {
    extern __shared__ float Vs[];
    __shared__ float wsums[NTHREADS / 32];
    __shared__ int is_last;

    const int bx = blockIdx.x;
    const int plane = bx / NSTRIPS;
    const int strip = bx - plane * NSTRIPS;
    const int r0 = strip * STRIP_ROWS;
    const int t = threadIdx.x;

    // Zero halos: per (field,row), positions [0..5] (cols -6..-1) and
    // [518..527] (cols >= 512). 16 floats per field-row.
    for (int idx = t; idx < NFIELDS * CROWS * 16; idx += NTHREADS) {
        int fr = idx >> 4, e = idx & 15;
        Vs[fr * ROWF + ((e < 6) ? e : (512 + e))] = 0.0f;
    }

    // Thread t owns cols 4t..4t+3 -> one ulonglong2 (two f32x2 lanes) per row
    const ulonglong2* __restrict__ p1 =
        (const ulonglong2*)img1 + (size_t)plane * (IMG_H * ROWQ) + t;
    const ulonglong2* __restrict__ p2 =
        (const ulonglong2*)img2 + (size_t)plane * (IMG_H * ROWQ) + t;

    const ull Wp[6] = {pack2(G0, G0), pack2(G1, G1), pack2(G2, G2),
                       pack2(G3, G3), pack2(G4, G4), pack2(G5, G5)};

    auto loadrow = [&](int row, ulonglong2& A, ulonglong2& B) {
        if ((unsigned)row < IMG_H) {
            A = p1[(size_t)row * ROWQ];
            B = p2[(size_t)row * ROWQ];
        } else { A.x = A.y = B.x = B.y = 0ull; }
    };

    float accv = 0.0f;

    ulonglong2 A, B;
    loadrow(r0 - 5, A, B);   // prefetch first input row

    __syncthreads();         // halo zeros visible

    for (int c = 0; c < NCHUNKS; ++c) {
        const int R = r0 + c * CROWS;    // first output row of this chunk

        // ---- Vertical scatter: 14 input rows -> 4 output accumulators,
        //      two f32x2 column streams per thread ----
        ull acc[NFIELDS][CROWS][2];
#pragma unroll
        for (int f = 0; f < NFIELDS; ++f)
#pragma unroll
            for (int j = 0; j < CROWS; ++j) { acc[f][j][0] = 0ull; acc[f][j][1] = 0ull; }

#pragma unroll
        for (int i = 0; i < CROWS + 10; ++i) {
            const ulonglong2 PA = A, PB = B;     // input row R-5+i
            // Prefetch next row (i==13 prefetches next chunk's first row R-1)
            {
                const int nrow = (i < CROWS + 9) ? (R - 4 + i) : (R - 1);
                loadrow(nrow, A, B);
            }

            const ull pu0 = fma2(PA.x, PA.x, mul2(PB.x, PB.x));
            const ull pv0 = mul2(PA.x, PB.x);
            const ull pu1 = fma2(PA.y, PA.y, mul2(PB.y, PB.y));
            const ull pv1 = mul2(PA.y, PB.y);

            const int jlo = (i - 10 > 0) ? (i - 10) : 0;
            const int jhi = (i < CROWS - 1) ? i : (CROWS - 1);
#pragma unroll
            for (int j = jlo; j <= jhi; ++j) {
                const int k = i - j;                    // 0..10
                const int wi = (k < 6) ? k : 10 - k;    // symmetric weight
                acc[0][j][0] = fma2(PA.x, Wp[wi], acc[0][j][0]);
                acc[0][j][1] = fma2(PA.y, Wp[wi], acc[0][j][1]);
                acc[1][j][0] = fma2(PB.x, Wp[wi], acc[1][j][0]);
                acc[1][j][1] = fma2(PB.y, Wp[wi], acc[1][j][1]);
                acc[2][j][0] = fma2(pu0, Wp[wi], acc[2][j][0]);
                acc[2][j][1] = fma2(pu1, Wp[wi], acc[2][j][1]);
                acc[3][j][0] = fma2(pv0, Wp[wi], acc[3][j][0]);
                acc[3][j][1] = fma2(pv1, Wp[wi], acc[3][j][1]);
            }
        }

        // Store V rows to shared: col 4t at position 6+4t -> 8B-aligned,
        // two STS.64 per field-row, lane stride 16B -> conflict-free.
#pragma unroll
        for (int j = 0; j < CROWS; ++j) {
            const int off = j * ROWF + 6 + 4 * t;
#pragma unroll
            for (int f = 0; f < NFIELDS; ++f) {
                float* base = Vs + f * CROWS * ROWF + off;
                *(ull*)(base) = acc[f][j][0];
                *(ull*)(base + 2) = acc[f][j][1];
            }
        }

        __syncthreads();   // V rows visible

        // ---- Horizontal + SSIM: 4 rows x 128 groups of 4 px = 512 jobs ----
#pragma unroll
        for (int rd = 0; rd < 4; ++rd) {
            const int job = t + rd * NTHREADS;
            const int row = job >> 7;      // 0..3
            const int g = job & 127;
            const float* base = Vs + row * ROWF + 4 * g;
            float m1[4], m2[4], uu[4], vv[4];
            hconv4(base + 0 * CROWS * ROWF, m1);
            hconv4(base + 1 * CROWS * ROWF, m2);
            hconv4(base + 2 * CROWS * ROWF, uu);
            hconv4(base + 3 * CROWS * ROWF, vv);
            if (R + row < IMG_H) {
#pragma unroll
                for (int p = 0; p < 4; ++p)
                    accv += ssim_px(m1[p], m2[p], uu[p], vv[p]);
            }
        }
        __syncthreads();   // horizontal reads done before next chunk's STS
    }

    // ---- Deterministic block reduction ----
#pragma unroll
    for (int off = 16; off; off >>= 1)
        accv += __shfl_xor_sync(FULLM, accv, off);
    if ((t & 31) == 0) wsums[t >> 5] = accv;
    __syncthreads();
    if (t == 0) {
        float s = 0.0f;
#pragma unroll
        for (int i = 0; i < NTHREADS / 32; ++i) s += wsums[i];
        g_partials[bx] = (double)s;
        __threadfence();
        unsigned old = atomicAdd(&g_arrive, 1u);
        is_last = (old == NBLOCKS - 1) ? 1 : 0;
    }
    __syncthreads();

    // ---- Fused deterministic finalize (last-arriving block, warp 0) ----
    if (is_last && t < 32) {
        __threadfence();
        double s = 0.0;
#pragma unroll
        for (int k = 0; k < NBLOCKS / 32; ++k) s += g_partials[t + 32 * k];
#pragma unroll
        for (int off = 16; off; off >>= 1)
            s += __shfl_xor_sync(FULLM, s, off);
        if (t == 0) {
            out[0] = (float)(1.0 - s / 12582912.0);   // 16*3*512*512
            g_arrive = 0;   // reset for next graph replay
        }
    }
}

extern "C" void kernel_launch(void* const* d_in, const int* in_sizes, int n_in,
                              void* d_out, int out_size) {
    const float* img1 = (const float*)d_in[0];
    const float* img2 = (const float*)d_in[1];
    // d_in[2] (gaussian window) is deterministic; weights baked in as immediates.
    cudaFuncSetAttribute(ssim_main, cudaFuncAttributeMaxDynamicSharedMemorySize,
                         SMEM_BYTES);
    ssim_main<<<NBLOCKS, NTHREADS, SMEM_BYTES>>>(img1, img2, (float*)d_out);
}

// round 14
// speedup vs baseline: 1.4742x; 1.0005x over previous
#include <cuda_runtime.h>
#include <cuda_fp16.h>

typedef unsigned long long ull;
typedef unsigned int uint;

#define IMG_W 512
#define IMG_H 512
#define NPLANES 48            // 16 batch * 3 channels
#define NSTRIPS 12            // strips per plane
#define STRIP_ROWS 44         // 11 chunks of 4 rows (rows >= 512 masked)
#define NBLOCKS (NPLANES * NSTRIPS)   // 576 blocks, occ=4 -> one wave
#define NTHREADS 128          // each thread owns 4 adjacent columns
#define ROWQ 128              // ulonglong2 (4 floats) per 512-px image row
#define NCHUNKS 11
#define CROWS 4               // output rows per chunk
#define NFIELDS 4             // x, y, u=x^2+y^2, v=x*y

// V stored as half2: row-array of 264 half2 (uint). half2 index i holds cols
// (2i-6, 2i-5): 3 left-halo half2 (cols -6..-1, zero), 256 data, 5 right
// (cols 512..521, zero). Horizontal window for cols 4g..4g+3 = W[0..7] at
// indices 2g..2g+7 -> four 8B-aligned LDS.64, conflict-free.
// Stores go through TWO STS.32 (uint index 3+2t is odd -> 8B store would trap).
#define ROWH 264
#define SMEM_UINTS (NFIELDS * CROWS * ROWH)
#define SMEM_BYTES (SMEM_UINTS * 4)   // 16896 -> occ 4 easily

#define SSIM_C1 0.0001f
#define SSIM_C2 0.0009f

// 1D gaussian (sigma=1.5, 11 taps, normalized) as literals -> FFMA-imm (rt=1)
#define G0 0.00102836f
#define G1 0.00759863f
#define G2 0.03600078f
#define G3 0.10936075f
#define G4 0.21300559f
#define G5 0.26601179f

#define FULLM 0xffffffffu

__device__ double g_partials[NBLOCKS];
__device__ unsigned g_arrive = 0;

__device__ __forceinline__ ull pack2(float x, float y) {
    ull r; asm("mov.b64 %0, {%1,%2};" : "=l"(r) : "f"(x), "f"(y)); return r;
}
__device__ __forceinline__ void un2(ull v, float& x, float& y) {
    asm("mov.b64 {%0,%1}, %2;" : "=f"(x), "=f"(y) : "l"(v));
}
__device__ __forceinline__ ull mul2(ull a, ull b) {
    ull d; asm("mul.rn.f32x2 %0, %1, %2;" : "=l"(d) : "l"(a), "l"(b)); return d;
}
__device__ __forceinline__ ull fma2(ull a, ull b, ull c) {
    ull d; asm("fma.rn.f32x2 %0, %1, %2, %3;" : "=l"(d) : "l"(a), "l"(b), "l"(c)); return d;
}
__device__ __forceinline__ __half2 u2h(uint v) {
    __half2 h; *(uint*)&h = v; return h;
}
__device__ __forceinline__ uint h2u(__half2 h) { return *(uint*)&h; }

// SSIM from the 4 convolved fields (fp32): mu1, mu2, euu=E[x^2+y^2], exy=E[xy]
__device__ __forceinline__ float ssim_px(float mu1, float mu2, float euu, float exy) {
    float msq = mu1 * mu1;
    msq = fmaf(mu2, mu2, msq);           // mu1^2 + mu2^2
    float m12 = mu1 * mu2;
    float ssum = euu - msq;              // sig1^2 + sig2^2
    float s12  = exy - m12;
    float num = fmaf(2.0f, m12, SSIM_C1) * fmaf(2.0f, s12, SSIM_C2);
    float den = (msq + SSIM_C1) * (ssum + SSIM_C2);
    return __fdividef(num, den);
}

__global__ void __launch_bounds__(NTHREADS, 4)
ssim_main(const float* __restrict__ img1, const float* __restrict__ img2,
          float* __restrict__ out) {
    extern __shared__ uint Vh[];
    __shared__ float wsums[NTHREADS / 32];
    __shared__ int is_last;

    const int bx = blockIdx.x;
    const int plane = bx / NSTRIPS;
    const int strip = bx - plane * NSTRIPS;
    const int r0 = strip * STRIP_ROWS;
    const int t = threadIdx.x;

    // Zero halos: per row-array, half2 indices 0..2 and 259..263 (8 each)
    for (int idx = t; idx < NFIELDS * CROWS * 8; idx += NTHREADS) {
        int ar = idx >> 3, e = idx & 7;
        Vh[ar * ROWH + ((e < 3) ? e : (256 + e))] = 0u;
    }

    // Thread t owns cols 4t..4t+3 -> one ulonglong2 (two f32x2 lanes) per row
    const ulonglong2* __restrict__ p1 =
        (const ulonglong2*)img1 + (size_t)plane * (IMG_H * ROWQ) + t;
    const ulonglong2* __restrict__ p2 =
        (const ulonglong2*)img2 + (size_t)plane * (IMG_H * ROWQ) + t;

    const ull Wp[6] = {pack2(G0, G0), pack2(G1, G1), pack2(G2, G2),
                       pack2(G3, G3), pack2(G4, G4), pack2(G5, G5)};
    const __half2 wh[6] = {__floats2half2_rn(G0, G0), __floats2half2_rn(G1, G1),
                           __floats2half2_rn(G2, G2), __floats2half2_rn(G3, G3),
                           __floats2half2_rn(G4, G4), __floats2half2_rn(G5, G5)};

    auto loadrow = [&](int row, ulonglong2& A, ulonglong2& B) {
        if ((unsigned)row < IMG_H) {
            A = p1[(size_t)row * ROWQ];
            B = p2[(size_t)row * ROWQ];
        } else { A.x = A.y = B.x = B.y = 0ull; }
    };

    float accv = 0.0f;

    ulonglong2 A, B;
    loadrow(r0 - 5, A, B);   // prefetch first input row

    __syncthreads();         // halo zeros visible

    for (int c = 0; c < NCHUNKS; ++c) {
        const int R = r0 + c * CROWS;    // first output row of this chunk

        // ---- Vertical scatter (fp32/f32x2, unchanged from R9) ----
        ull acc[NFIELDS][CROWS][2];
#pragma unroll
        for (int f = 0; f < NFIELDS; ++f)
#pragma unroll
            for (int j = 0; j < CROWS; ++j) { acc[f][j][0] = 0ull; acc[f][j][1] = 0ull; }

#pragma unroll
        for (int i = 0; i < CROWS + 10; ++i) {
            const ulonglong2 PA = A, PB = B;     // input row R-5+i
            {   // prefetch next row (i==13 prefetches next chunk's first row R-1)
                const int nrow = (i < CROWS + 9) ? (R - 4 + i) : (R - 1);
                loadrow(nrow, A, B);
            }
            const ull pu0 = fma2(PA.x, PA.x, mul2(PB.x, PB.x));
            const ull pv0 = mul2(PA.x, PB.x);
            const ull pu1 = fma2(PA.y, PA.y, mul2(PB.y, PB.y));
            const ull pv1 = mul2(PA.y, PB.y);

            const int jlo = (i - 10 > 0) ? (i - 10) : 0;
            const int jhi = (i < CROWS - 1) ? i : (CROWS - 1);
#pragma unroll
            for (int j = jlo; j <= jhi; ++j) {
                const int k = i - j;                    // 0..10
                const int wi = (k < 6) ? k : 10 - k;    // symmetric weight
                acc[0][j][0] = fma2(PA.x, Wp[wi], acc[0][j][0]);
                acc[0][j][1] = fma2(PA.y, Wp[wi], acc[0][j][1]);
                acc[1][j][0] = fma2(PB.x, Wp[wi], acc[1][j][0]);
                acc[1][j][1] = fma2(PB.y, Wp[wi], acc[1][j][1]);
                acc[2][j][0] = fma2(pu0, Wp[wi], acc[2][j][0]);
                acc[2][j][1] = fma2(pu1, Wp[wi], acc[2][j][1]);
                acc[3][j][0] = fma2(pv0, Wp[wi], acc[3][j][0]);
                acc[3][j][1] = fma2(pv1, Wp[wi], acc[3][j][1]);
            }
        }

        // ---- Convert to half2 and store: cols (4t,4t+1),(4t+2,4t+3) at
        //      half2 indices 3+2t, 4+2t. Index is ODD -> two STS.32 (4B
        //      aligned), NOT one STS.64 (would be a misaligned 8B store). ----
#pragma unroll
        for (int j = 0; j < CROWS; ++j) {
#pragma unroll
            for (int f = 0; f < NFIELDS; ++f) {
                float x0, x1, x2, x3;
                un2(acc[f][j][0], x0, x1);
                un2(acc[f][j][1], x2, x3);
                uint* dst = Vh + (f * CROWS + j) * ROWH + 3 + 2 * t;
                dst[0] = h2u(__floats2half2_rn(x0, x1));   // cols (4t, 4t+1)
                dst[1] = h2u(__floats2half2_rn(x2, x3));   // cols (4t+2, 4t+3)
            }
        }
        __syncthreads();   // V rows visible

        // ---- Horizontal (HFMA2 on half2 pairs) + SSIM (fp32) ----
        // Job = 4 px (cols 4t..4t+3) of row rd. Even pairs W[m] = cols
        // (4g-6+2m, 4g-5+2m); odd pairs O[a] built by PRMT from W[a],W[a+1].
#pragma unroll
        for (int rd = 0; rd < 4; ++rd) {
            const int row = rd;
            const int g = t;
            float vals[NFIELDS][4];
#pragma unroll
            for (int f = 0; f < NFIELDS; ++f) {
                const uint* rowp = Vh + (f * CROWS + row) * ROWH + 2 * g;  // even -> 8B aligned
                uint2 q0 = *(const uint2*)(rowp);
                uint2 q1 = *(const uint2*)(rowp + 2);
                uint2 q2 = *(const uint2*)(rowp + 4);
                uint2 q3 = *(const uint2*)(rowp + 6);
                const uint W0 = q0.x, W1 = q0.y, W2 = q1.x, W3 = q1.y;
                const uint W4 = q2.x, W5 = q2.y, W6 = q3.x, W7 = q3.y;
                const uint O0 = __byte_perm(W0, W1, 0x5432);
                const uint O1 = __byte_perm(W1, W2, 0x5432);
                const uint O2 = __byte_perm(W2, W3, 0x5432);
                const uint O3 = __byte_perm(W3, W4, 0x5432);
                const uint O4 = __byte_perm(W4, W5, 0x5432);
                const uint O5 = __byte_perm(W5, W6, 0x5432);
                const uint O6 = __byte_perm(W6, W7, 0x5432);

                // pair A = outputs (4g, 4g+1)
                __half2 hA = __hmul2(u2h(O0), wh[0]);
                hA = __hfma2(u2h(W1), wh[1], hA);
                hA = __hfma2(u2h(O1), wh[2], hA);
                hA = __hfma2(u2h(W2), wh[3], hA);
                hA = __hfma2(u2h(O2), wh[4], hA);
                hA = __hfma2(u2h(W3), wh[5], hA);
                hA = __hfma2(u2h(O3), wh[4], hA);
                hA = __hfma2(u2h(W4), wh[3], hA);
                hA = __hfma2(u2h(O4), wh[2], hA);
                hA = __hfma2(u2h(W5), wh[1], hA);
                hA = __hfma2(u2h(O5), wh[0], hA);
                // pair B = outputs (4g+2, 4g+3)
                __half2 hB = __hmul2(u2h(O1), wh[0]);
                hB = __hfma2(u2h(W2), wh[1], hB);
                hB = __hfma2(u2h(O2), wh[2], hB);
                hB = __hfma2(u2h(W3), wh[3], hB);
                hB = __hfma2(u2h(O3), wh[4], hB);
                hB = __hfma2(u2h(W4), wh[5], hB);
                hB = __hfma2(u2h(O4), wh[4], hB);
                hB = __hfma2(u2h(W5), wh[3], hB);
                hB = __hfma2(u2h(O5), wh[2], hB);
                hB = __hfma2(u2h(W6), wh[1], hB);
                hB = __hfma2(u2h(O6), wh[0], hB);

                float2 fa = __half22float2(hA);
                float2 fb = __half22float2(hB);
                vals[f][0] = fa.x; vals[f][1] = fa.y;
                vals[f][2] = fb.x; vals[f][3] = fb.y;
            }
            if (R + row < IMG_H) {
#pragma unroll
                for (int p = 0; p < 4; ++p)
                    accv += ssim_px(vals[0][p], vals[1][p], vals[2][p], vals[3][p]);
            }
        }
        __syncthreads();   // horizontal reads done before next chunk's STS
    }

    // ---- Deterministic block reduction ----
#pragma unroll
    for (int off = 16; off; off >>= 1)
        accv += __shfl_xor_sync(FULLM, accv, off);
    if ((t & 31) == 0) wsums[t >> 5] = accv;
    __syncthreads();
    if (t == 0) {
        float s = 0.0f;
#pragma unroll
        for (int i = 0; i < NTHREADS / 32; ++i) s += wsums[i];
        g_partials[bx] = (double)s;
        __threadfence();
        unsigned old = atomicAdd(&g_arrive, 1u);
        is_last = (old == NBLOCKS - 1) ? 1 : 0;
    }
    __syncthreads();

    // ---- Fused deterministic finalize (last-arriving block, warp 0) ----
    if (is_last && t < 32) {
        __threadfence();
        double s = 0.0;
#pragma unroll
        for (int k = 0; k < NBLOCKS / 32; ++k) s += g_partials[t + 32 * k];
#pragma unroll
        for (int off = 16; off; off >>= 1)
            s += __shfl_xor_sync(FULLM, s, off);
        if (t == 0) {
            out[0] = (float)(1.0 - s / 12582912.0);   // 16*3*512*512
            g_arrive = 0;   // reset for next graph replay
        }
    }
}

extern "C" void kernel_launch(void* const* d_in, const int* in_sizes, int n_in,
                              void* d_out, int out_size) {
    const float* img1 = (const float*)d_in[0];
    const float* img2 = (const float*)d_in[1];
    // d_in[2] (gaussian window) is deterministic; weights baked in as immediates.
    cudaFuncSetAttribute(ssim_main, cudaFuncAttributeMaxDynamicSharedMemorySize,
                         SMEM_BYTES);
    ssim_main<<<NBLOCKS, NTHREADS, SMEM_BYTES>>>(img1, img2, (float*)d_out);
}

// round 15
// speedup vs baseline: 1.4765x; 1.0015x over previous
#include <cuda_runtime.h>
#include <cuda_fp16.h>

typedef unsigned long long ull;
typedef unsigned int uint;

#define IMG_W 512
#define IMG_H 512
#define NPLANES 48            // 16 batch * 3 channels
#define NSTRIPS 12            // strips per plane
#define STRIP_ROWS 44         // 11 chunks of 4 rows (rows >= 512 masked)
#define NBLOCKS (NPLANES * NSTRIPS)   // 576 blocks, occ=4 -> one wave
#define NTHREADS 128          // each thread owns 4 adjacent columns
#define ROWQ 128              // ulonglong2 (4 floats) per 512-px image row
#define NCHUNKS 11
#define CROWS 4               // output rows per chunk
#define NFIELDS 4             // x, y, u=x^2+y^2, v=x*y

// V stored as half2, DOUBLE-BUFFERED (buf = c&1): per buffer, 16 row-arrays
// of 264 half2. half2 index i holds cols (2i-6, 2i-5): 3 left-halo half2
// (zero), 256 data, 5 right (zero). Window for cols 4g..4g+3 = W[0..7] at
// indices 2g..2g+7 -> four 8B-aligned LDS.64, conflict-free. Stores are two
// STS.32 (odd half2 index -> an 8B store would trap on alignment).
// ONE barrier per chunk: vertical(c) -> STS(buf c&1) -> bar -> horizontal(c).
// WAR-safe: STS for chunk c+2 (same buf) happens after bar(c+1), which
// implies all threads finished consuming chunk c.
#define ROWH 264
#define BUF_UINTS (NFIELDS * CROWS * ROWH)
#define SMEM_BYTES (2 * BUF_UINTS * 4)   // 33792 -> occ 4 (135KB/SM)

#define SSIM_C1 0.0001f
#define SSIM_C2 0.0009f

// 1D gaussian (sigma=1.5, 11 taps, normalized) as literals -> FFMA-imm (rt=1)
#define G0 0.00102836f
#define G1 0.00759863f
#define G2 0.03600078f
#define G3 0.10936075f
#define G4 0.21300559f
#define G5 0.26601179f

#define FULLM 0xffffffffu

__device__ double g_partials[NBLOCKS];
__device__ unsigned g_arrive = 0;

__device__ __forceinline__ ull pack2(float x, float y) {
    ull r; asm("mov.b64 %0, {%1,%2};" : "=l"(r) : "f"(x), "f"(y)); return r;
}
__device__ __forceinline__ void un2(ull v, float& x, float& y) {
    asm("mov.b64 {%0,%1}, %2;" : "=f"(x), "=f"(y) : "l"(v));
}
__device__ __forceinline__ ull mul2(ull a, ull b) {
    ull d; asm("mul.rn.f32x2 %0, %1, %2;" : "=l"(d) : "l"(a), "l"(b)); return d;
}
__device__ __forceinline__ ull fma2(ull a, ull b, ull c) {
    ull d; asm("fma.rn.f32x2 %0, %1, %2, %3;" : "=l"(d) : "l"(a), "l"(b), "l"(c)); return d;
}
__device__ __forceinline__ __half2 u2h(uint v) {
    __half2 h; *(uint*)&h = v; return h;
}
__device__ __forceinline__ uint h2u(__half2 h) { return *(uint*)&h; }

// SSIM from the 4 convolved fields (fp32): mu1, mu2, euu=E[x^2+y^2], exy=E[xy]
__device__ __forceinline__ float ssim_px(float mu1, float mu2, float euu, float exy) {
    float msq = mu1 * mu1;
    msq = fmaf(mu2, mu2, msq);           // mu1^2 + mu2^2
    float m12 = mu1 * mu2;
    float ssum = euu - msq;              // sig1^2 + sig2^2
    float s12  = exy - m12;
    float num = fmaf(2.0f, m12, SSIM_C1) * fmaf(2.0f, s12, SSIM_C2);
    float den = (msq + SSIM_C1) * (ssum + SSIM_C2);
    return __fdividef(num, den);
}

__global__ void __launch_bounds__(NTHREADS, 4)
ssim_main(const float* __restrict__ img1, const float* __restrict__ img2,
          float* __restrict__ out) {
    extern __shared__ uint Vh[];
    __shared__ float wsums[NTHREADS / 32];
    __shared__ int is_last;

    const int bx = blockIdx.x;
    const int plane = bx / NSTRIPS;
    const int strip = bx - plane * NSTRIPS;
    const int r0 = strip * STRIP_ROWS;
    const int t = threadIdx.x;

    // Zero halos of BOTH buffers: 32 row-arrays, half2 indices 0..2 & 259..263
    for (int idx = t; idx < 2 * NFIELDS * CROWS * 8; idx += NTHREADS) {
        int ar = idx >> 3, e = idx & 7;
        Vh[ar * ROWH + ((e < 3) ? e : (256 + e))] = 0u;
    }

    // Thread t owns cols 4t..4t+3 -> one ulonglong2 (two f32x2 lanes) per row
    const ulonglong2* __restrict__ p1 =
        (const ulonglong2*)img1 + (size_t)plane * (IMG_H * ROWQ) + t;
    const ulonglong2* __restrict__ p2 =
        (const ulonglong2*)img2 + (size_t)plane * (IMG_H * ROWQ) + t;

    const ull Wp[6] = {pack2(G0, G0), pack2(G1, G1), pack2(G2, G2),
                       pack2(G3, G3), pack2(G4, G4), pack2(G5, G5)};
    const __half2 wh[6] = {__floats2half2_rn(G0, G0), __floats2half2_rn(G1, G1),
                           __floats2half2_rn(G2, G2), __floats2half2_rn(G3, G3),
                           __floats2half2_rn(G4, G4), __floats2half2_rn(G5, G5)};

    auto loadrow = [&](int row, ulonglong2& A, ulonglong2& B) {
        if ((unsigned)row < IMG_H) {
            A = p1[(size_t)row * ROWQ];
            B = p2[(size_t)row * ROWQ];
        } else { A.x = A.y = B.x = B.y = 0ull; }
    };

    float accv = 0.0f;

    ulonglong2 A, B;
    loadrow(r0 - 5, A, B);   // prefetch first input row

    for (int c = 0; c < NCHUNKS; ++c) {
        const int R = r0 + c * CROWS;    // first output row of this chunk
        uint* buf = Vh + (c & 1) * BUF_UINTS;

        // ---- Vertical scatter (fp32/f32x2) ----
        ull acc[NFIELDS][CROWS][2];
#pragma unroll
        for (int f = 0; f < NFIELDS; ++f)
#pragma unroll
            for (int j = 0; j < CROWS; ++j) { acc[f][j][0] = 0ull; acc[f][j][1] = 0ull; }

#pragma unroll
        for (int i = 0; i < CROWS + 10; ++i) {
            const ulonglong2 PA = A, PB = B;     // input row R-5+i
            {   // prefetch next row (i==13 prefetches next chunk's first row R-1)
                const int nrow = (i < CROWS + 9) ? (R - 4 + i) : (R - 1);
                loadrow(nrow, A, B);
            }
            const ull pu0 = fma2(PA.x, PA.x, mul2(PB.x, PB.x));
            const ull pv0 = mul2(PA.x, PB.x);
            const ull pu1 = fma2(PA.y, PA.y, mul2(PB.y, PB.y));
            const ull pv1 = mul2(PA.y, PB.y);

            const int jlo = (i - 10 > 0) ? (i - 10) : 0;
            const int jhi = (i < CROWS - 1) ? i : (CROWS - 1);
#pragma unroll
            for (int j = jlo; j <= jhi; ++j) {
                const int k = i - j;                    // 0..10
                const int wi = (k < 6) ? k : 10 - k;    // symmetric weight
                acc[0][j][0] = fma2(PA.x, Wp[wi], acc[0][j][0]);
                acc[0][j][1] = fma2(PA.y, Wp[wi], acc[0][j][1]);
                acc[1][j][0] = fma2(PB.x, Wp[wi], acc[1][j][0]);
                acc[1][j][1] = fma2(PB.y, Wp[wi], acc[1][j][1]);
                acc[2][j][0] = fma2(pu0, Wp[wi], acc[2][j][0]);
                acc[2][j][1] = fma2(pu1, Wp[wi], acc[2][j][1]);
                acc[3][j][0] = fma2(pv0, Wp[wi], acc[3][j][0]);
                acc[3][j][1] = fma2(pv1, Wp[wi], acc[3][j][1]);
            }
        }

        // ---- Convert to half2 and store into this chunk's buffer ----
#pragma unroll
        for (int j = 0; j < CROWS; ++j) {
#pragma unroll
            for (int f = 0; f < NFIELDS; ++f) {
                float x0, x1, x2, x3;
                un2(acc[f][j][0], x0, x1);
                un2(acc[f][j][1], x2, x3);
                uint* dst = buf + (f * CROWS + j) * ROWH + 3 + 2 * t;
                dst[0] = h2u(__floats2half2_rn(x0, x1));   // cols (4t, 4t+1)
                dst[1] = h2u(__floats2half2_rn(x2, x3));   // cols (4t+2, 4t+3)
            }
        }
        __syncthreads();   // single barrier per chunk (double-buffered WAR-safe)

        // ---- Horizontal (HFMA2 on half2 pairs) + SSIM (fp32) ----
#pragma unroll
        for (int rd = 0; rd < 4; ++rd) {
            const int row = rd;
            const int g = t;
            float vals[NFIELDS][4];
#pragma unroll
            for (int f = 0; f < NFIELDS; ++f) {
                const uint* rowp = buf + (f * CROWS + row) * ROWH + 2 * g;  // even -> 8B aligned
                uint2 q0 = *(const uint2*)(rowp);
                uint2 q1 = *(const uint2*)(rowp + 2);
                uint2 q2 = *(const uint2*)(rowp + 4);
                uint2 q3 = *(const uint2*)(rowp + 6);
                const uint W0 = q0.x, W1 = q0.y, W2 = q1.x, W3 = q1.y;
                const uint W4 = q2.x, W5 = q2.y, W6 = q3.x, W7 = q3.y;
                const uint O0 = __byte_perm(W0, W1, 0x5432);
                const uint O1 = __byte_perm(W1, W2, 0x5432);
                const uint O2 = __byte_perm(W2, W3, 0x5432);
                const uint O3 = __byte_perm(W3, W4, 0x5432);
                const uint O4 = __byte_perm(W4, W5, 0x5432);
                const uint O5 = __byte_perm(W5, W6, 0x5432);
                const uint O6 = __byte_perm(W6, W7, 0x5432);

                // pair A = outputs (4g, 4g+1)
                __half2 hA = __hmul2(u2h(O0), wh[0]);
                hA = __hfma2(u2h(W1), wh[1], hA);
                hA = __hfma2(u2h(O1), wh[2], hA);
                hA = __hfma2(u2h(W2), wh[3], hA);
                hA = __hfma2(u2h(O2), wh[4], hA);
                hA = __hfma2(u2h(W3), wh[5], hA);
                hA = __hfma2(u2h(O3), wh[4], hA);
                hA = __hfma2(u2h(W4), wh[3], hA);
                hA = __hfma2(u2h(O4), wh[2], hA);
                hA = __hfma2(u2h(W5), wh[1], hA);
                hA = __hfma2(u2h(O5), wh[0], hA);
                // pair B = outputs (4g+2, 4g+3)
                __half2 hB = __hmul2(u2h(O1), wh[0]);
                hB = __hfma2(u2h(W2), wh[1], hB);
                hB = __hfma2(u2h(O2), wh[2], hB);
                hB = __hfma2(u2h(W3), wh[3], hB);
                hB = __hfma2(u2h(O3), wh[4], hB);
                hB = __hfma2(u2h(W4), wh[5], hB);
                hB = __hfma2(u2h(O4), wh[4], hB);
                hB = __hfma2(u2h(W5), wh[3], hB);
                hB = __hfma2(u2h(O5), wh[2], hB);
                hB = __hfma2(u2h(W6), wh[1], hB);
                hB = __hfma2(u2h(O6), wh[0], hB);

                float2 fa = __half22float2(hA);
                float2 fb = __half22float2(hB);
                vals[f][0] = fa.x; vals[f][1] = fa.y;
                vals[f][2] = fb.x; vals[f][3] = fb.y;
            }
            if (R + row < IMG_H) {
#pragma unroll
                for (int p = 0; p < 4; ++p)
                    accv += ssim_px(vals[0][p], vals[1][p], vals[2][p], vals[3][p]);
            }
        }
        // NO second barrier: next chunk writes the other buffer; the c+2
        // reuse of this buffer is ordered by the next chunk's barrier.
    }

    // ---- Deterministic block reduction ----
#pragma unroll
    for (int off = 16; off; off >>= 1)
        accv += __shfl_xor_sync(FULLM, accv, off);
    if ((t & 31) == 0) wsums[t >> 5] = accv;
    __syncthreads();
    if (t == 0) {
        float s = 0.0f;
#pragma unroll
        for (int i = 0; i < NTHREADS / 32; ++i) s += wsums[i];
        g_partials[bx] = (double)s;
        __threadfence();
        unsigned old = atomicAdd(&g_arrive, 1u);
        is_last = (old == NBLOCKS - 1) ? 1 : 0;
    }
    __syncthreads();

    // ---- Fused deterministic finalize (last-arriving block, warp 0) ----
    if (is_last && t < 32) {
        __threadfence();
        double s = 0.0;
#pragma unroll
        for (int k = 0; k < NBLOCKS / 32; ++k) s += g_partials[t + 32 * k];
#pragma unroll
        for (int off = 16; off; off >>= 1)
            s += __shfl_xor_sync(FULLM, s, off);
        if (t == 0) {
            out[0] = (float)(1.0 - s / 12582912.0);   // 16*3*512*512
            g_arrive = 0;   // reset for next graph replay
        }
    }
}

extern "C" void kernel_launch(void* const* d_in, const int* in_sizes, int n_in,
                              void* d_out, int out_size) {
    const float* img1 = (const float*)d_in[0];
    const float* img2 = (const float*)d_in[1];
    // d_in[2] (gaussian window) is deterministic; weights baked in as immediates.
    cudaFuncSetAttribute(ssim_main, cudaFuncAttributeMaxDynamicSharedMemorySize,
                         SMEM_BYTES);
    ssim_main<<<NBLOCKS, NTHREADS, SMEM_BYTES>>>(img1, img2, (float*)d_out);
}